// round 4
// baseline (speedup 1.0000x reference)
#include <cuda_runtime.h>
#include <cuda_bf16.h>

typedef unsigned long long u64;

#define Bb 8
#define Hh 32
#define Ff 8
#define Xx 128
#define Tt 256
#define Ts 255

// ---------------- device scratch (no allocation allowed) ----------------
__device__ float  g_Gz0[Bb*Hh*Xx*Ff];                 // [b][c][x][f]
__device__ float  g_dD[(size_t)Bb*Hh*Ts*Xx];          // [b][c][t][x]
__device__ float4 g_W4[(size_t)Xx*Hh*16*Hh];          // [k][c][jp][i]
__device__ float2 g_dx[(size_t)Xx*Ts*Hh*Bb];          // [k][t][c][b]
__device__ float2 g_zinit[Xx*Hh*Bb];                  // [k][h][b]
__device__ float2 g_zall[(size_t)Bb*Hh*Tt*Xx];        // [bh][t][k]
__device__ float2 g_twf[127], g_twi[127];

// ---------------- f32x2 helpers ----------------
__device__ __forceinline__ u64 f2fma(u64 a,u64 b,u64 c){u64 d;asm("fma.rn.f32x2 %0,%1,%2,%3;":"=l"(d):"l"(a),"l"(b),"l"(c));return d;}
__device__ __forceinline__ u64 f2add(u64 a,u64 b){u64 d;asm("add.rn.f32x2 %0,%1,%2;":"=l"(d):"l"(a),"l"(b));return d;}
__device__ __forceinline__ u64 pk(float a,float b){u64 d;asm("mov.b64 %0,{%1,%2};":"=l"(d):"f"(a),"f"(b));return d;}
__device__ __forceinline__ u64 pkd(float a){u64 d;asm("mov.b64 %0,{%1,%1};":"=l"(d):"f"(a));return d;}
__device__ __forceinline__ void upk(u64 v,float&a,float&b){asm("mov.b64 {%0,%1},%2;":"=f"(a),"=f"(b):"l"(v));}

// ---------------- twiddles ----------------
__global__ void k_twiddle(){
    int t=threadIdx.x;
    if(t<127){
        int l=1<<(31-__clz(t+1)); int j=t+1-l;
        float s,c; sincospif((float)j/(float)l,&s,&c);
        g_twf[t]=make_float2(c,-s); g_twi[t]=make_float2(c,s);
    }
}

// ---------------- Stockham radix-2, 64 threads per FFT, nat order in/out ----
__device__ __forceinline__ float2* do_fft(float2* x,float2* y,const float2* tw,int bt){
    float2 *s=x,*d=y;
    #pragma unroll
    for(int st=0;st<7;st++){
        int l=1<<st, j=bt&(l-1), q=bt>>st;
        float2 aa=s[q*l+j], bb=s[q*l+j+64], w=tw[l-1+j];
        float br=w.x*bb.x-w.y*bb.y, bi=w.x*bb.y+w.y*bb.x;
        d[q*2*l+j]=make_float2(aa.x+br,aa.y+bi);
        d[q*2*l+j+l]=make_float2(aa.x-br,aa.y-bi);
        __syncthreads();
        float2* tmp=s; s=d; d=tmp;
    }
    return s;
}

// ---------------- Gz0[b][c][x][f] = sum_h Gw[c][f][h] z0[b][h][x] ------------
__global__ void k_gz0(const float* __restrict__ z0,const float* __restrict__ Gw){
    __shared__ float z0s[Hh][Xx];
    int blk=blockIdx.x, c=blk&31, b=blk>>5, x=threadIdx.x;
    for(int e=x;e<Hh*Xx;e+=128) z0s[e>>7][e&127]=z0[(size_t)b*Hh*Xx+e];
    __syncthreads();
    #pragma unroll
    for(int f=0;f<Ff;f++){
        float acc=0.f;
        #pragma unroll 8
        for(int h=0;h<Hh;h++) acc+=Gw[(c*Ff+f)*Hh+h]*z0s[h][x];
        g_Gz0[((size_t)blk*Xx+x)*Ff+f]=acc;
    }
}

// ---------------- W transpose: g_W4[k][c][jp][i] ----------------
__global__ void k_wt(const float* __restrict__ Wr,const float* __restrict__ Wi){
    int gid=blockIdx.x*256+threadIdx.x;            // 128*32*16*32 = 2097152
    int i=gid&31, jp=(gid>>5)&15, c=(gid>>9)&31, k=gid>>14;
    size_t s=(((size_t)k*Hh+i)*Hh+c)*Hh + 2*jp;
    g_W4[gid]=make_float4(Wr[s],Wi[s],Wr[s+1],Wi[s+1]);
}

// ---------------- dD[b][c][t][x] = sum_f Gz0*(xi[t+1]-xi[t]) ----------------
__global__ void k_dD(const float* __restrict__ xi){
    __shared__ float gs[Xx][Ff];
    int blk=blockIdx.x, c=blk&31, b=blk>>5, tid=threadIdx.x;
    for(int e=tid;e<Xx*Ff;e+=256) gs[e>>3][e&7]=g_Gz0[(size_t)blk*Xx*Ff+e];
    __syncthreads();
    if(tid<Ts){
        for(int xx=0;xx<Xx;xx++){
            float acc=0.f;
            #pragma unroll
            for(int f=0;f<Ff;f++){
                const float* p=xi+(((size_t)(b*Ff+f)*Xx)+xx)*Tt+tid;
                acc+=gs[xx][f]*(p[1]-p[0]);
            }
            g_dD[(((size_t)blk*Ts)+tid)*Xx+xx]=acc;
        }
    }
}

// ---------------- FFT of dD rows -> g_dx[k][t][c][b] ----------------
__global__ void k_fft_dx(){
    __shared__ float2 xb[4][128], yb[4][128], tws[127];
    int tid=threadIdx.x;
    for(int q=tid;q<127;q+=256) tws[q]=g_twf[q];
    int blk=blockIdx.x, tc=blk&63, bc=blk>>6, c=bc&31, b=bc>>5;
    for(int e=tid;e<512;e+=256){
        int sub=e>>7, xx=e&127, t=tc*4+sub;
        float v=(t<Ts)? g_dD[(((size_t)bc*Ts)+t)*Xx+xx] : 0.f;
        if(xx&1) v=-v;                              // fftshift
        xb[sub][xx]=make_float2(v,0.f);
    }
    __syncthreads();
    int sub=tid>>6, bt=tid&63;
    float2* r=do_fft(xb[sub],yb[sub],tws,bt);
    int t=tc*4+sub;
    if(t<Ts){
        g_dx[(((size_t)bt*Ts+t)*Hh+c)*Bb+b]=r[bt];
        g_dx[(((size_t)(bt+64)*Ts+t)*Hh+c)*Bb+b]=r[bt+64];
    }
}

// ---------------- FFT of z0 -> g_zinit[k][h][b] ----------------
__global__ void k_fft_z0(const float* __restrict__ z0){
    __shared__ float2 xb[4][128], yb[4][128], tws[127];
    int tid=threadIdx.x;
    for(int q=tid;q<127;q+=256) tws[q]=g_twf[q];
    int blk=blockIdx.x, hc=blk&7, b=blk>>3;
    for(int e=tid;e<512;e+=256){
        int sub=e>>7, xx=e&127, h=hc*4+sub;
        float v=z0[((size_t)b*Hh+h)*Xx+xx];
        if(xx&1) v=-v;
        xb[sub][xx]=make_float2(v,0.f);
    }
    __syncthreads();
    int sub=tid>>6, bt=tid&63, h=hc*4+sub;
    float2* r=do_fft(xb[sub],yb[sub],tws,bt);
    g_zinit[((size_t)bt*Hh+h)*Bb+b]=r[bt];
    g_zinit[((size_t)(bt+64)*Hh+h)*Bb+b]=r[bt+64];
}

// ---------------- the sequential CDE scan: one CTA per Fourier mode ---------
__global__ void __launch_bounds__(256,1) k_scan(){
    __shared__ __align__(16) float zre_s[Hh][Bb], zim_s[Hh][Bb];
    __shared__ __align__(16) float dxre_s[Hh][Bb], dxim_s[Hh][Bb], dxni_s[Hh][Bb];
    __shared__ float part_s[8][32][16];
    int tid=threadIdx.x, k=blockIdx.x;
    int cg=tid>>5, i=tid&31;
    int i2=tid>>3, b2=tid&7;
    {   float2 v=g_zinit[(size_t)k*256+tid];       // tid = h*8+b
        zre_s[i2][b2]=v.x; zim_s[i2][b2]=v.y;
        g_zall[((size_t)(b2*Hh+i2)*Tt+0)*Xx+k]=v;
    }
    const float4* Wk=g_W4+(size_t)k*16384;
    u64 m1=pkd(-1.f);
    for(int t=0;t<Ts;t++){
        __syncthreads();
        {   float2 v=g_dx[((size_t)k*Ts+t)*256+tid];
            dxre_s[i2][b2]=v.x; dxim_s[i2][b2]=v.y; dxni_s[i2][b2]=-v.y;
        }
        __syncthreads();
        u64 aRe[4]={0,0,0,0}, aIm[4]={0,0,0,0};
        for(int cc=0;cc<4;cc++){
            int c=cg*4+cc;
            u64 Arr[4]={0,0,0,0},Aii[4]={0,0,0,0},Ari[4]={0,0,0,0},Air[4]={0,0,0,0};
            const float4* Wc=Wk+c*512+i;
            #pragma unroll 4
            for(int jp=0;jp<16;jp++){
                float4 w=__ldg(&Wc[jp*32]);
                #pragma unroll
                for(int half=0;half<2;half++){
                    int j=2*jp+half;
                    u64 wr=pkd(half? w.z:w.x), wi=pkd(half? w.w:w.y);
                    float4 q0=*(const float4*)&zre_s[j][0];
                    float4 q1=*(const float4*)&zre_s[j][4];
                    float4 r0=*(const float4*)&zim_s[j][0];
                    float4 r1=*(const float4*)&zim_s[j][4];
                    u64 zr[4]={pk(q0.x,q0.y),pk(q0.z,q0.w),pk(q1.x,q1.y),pk(q1.z,q1.w)};
                    u64 zi[4]={pk(r0.x,r0.y),pk(r0.z,r0.w),pk(r1.x,r1.y),pk(r1.z,r1.w)};
                    #pragma unroll
                    for(int p=0;p<4;p++){
                        Arr[p]=f2fma(wr,zr[p],Arr[p]);
                        Aii[p]=f2fma(wi,zi[p],Aii[p]);
                        Ari[p]=f2fma(wr,zi[p],Ari[p]);
                        Air[p]=f2fma(wi,zr[p],Air[p]);
                    }
                }
            }
            #pragma unroll
            for(int p=0;p<4;p++){
                u64 sre=f2fma(Aii[p],m1,Arr[p]);
                u64 sim=f2add(Ari[p],Air[p]);
                u64 dre=*(const u64*)&dxre_s[c][2*p];
                u64 dim=*(const u64*)&dxim_s[c][2*p];
                u64 dni=*(const u64*)&dxni_s[c][2*p];
                aRe[p]=f2fma(dre,sre,aRe[p]); aRe[p]=f2fma(dni,sim,aRe[p]);
                aIm[p]=f2fma(dre,sim,aIm[p]); aIm[p]=f2fma(dim,sre,aIm[p]);
            }
        }
        #pragma unroll
        for(int p=0;p<4;p++){
            float x0,x1;
            upk(aRe[p],x0,x1); part_s[cg][i][4*p]=x0;   part_s[cg][i][4*p+2]=x1;
            upk(aIm[p],x0,x1); part_s[cg][i][4*p+1]=x0; part_s[cg][i][4*p+3]=x1;
        }
        __syncthreads();
        float sr=0.f,si=0.f;
        #pragma unroll
        for(int g=0;g<8;g++){ sr+=part_s[g][i2][2*b2]; si+=part_s[g][i2][2*b2+1]; }
        float nr=zre_s[i2][b2]+sr, ni=zim_s[i2][b2]+si;
        zre_s[i2][b2]=nr; zim_s[i2][b2]=ni;
        g_zall[((size_t)(b2*Hh+i2)*Tt+(t+1))*Xx+k]=make_float2(nr,ni);
    }
}

// ---------------- inverse FFT of z_all -> out[b][h][n][t] ----------------
__global__ void k_fft_out(float* __restrict__ out){
    __shared__ float2 xb[4][128], yb[4][128], tws[127];
    int tid=threadIdx.x;
    for(int q=tid;q<127;q+=256) tws[q]=g_twi[q];
    int blk=blockIdx.x, tc=blk&63, bh=blk>>6;
    for(int e=tid;e<512;e+=256){
        int sub=e>>7, kk=e&127, t=tc*4+sub;
        xb[sub][kk]=g_zall[((size_t)bh*Tt+t)*Xx+kk];
    }
    __syncthreads();
    int sub=tid>>6, bt=tid&63, t=tc*4+sub;
    float2* r=do_fft(xb[sub],yb[sub],tws,bt);
    const float sc=1.f/128.f;
    float s0=(bt&1)? -sc:sc;                        // ifftshift sign; bt+64 keeps parity of bt
    out[((size_t)bh*Xx+bt)*Tt+t]      = r[bt].x*s0;
    out[((size_t)bh*Xx+bt+64)*Tt+t]   = r[bt+64].x*s0;
}

// ---------------- launch ----------------
extern "C" void kernel_launch(void* const* d_in,const int* in_sizes,int n_in,
                              void* d_out,int out_size){
    const float* z0=(const float*)d_in[0];
    const float* xi=(const float*)d_in[1];
    // d_in[2] = A : algebraically dead (cancels in dX)
    const float* Gw=(const float*)d_in[3];
    const float* Wr=(const float*)d_in[4];
    const float* Wi=(const float*)d_in[5];
    float* out=(float*)d_out;

    k_twiddle<<<1,128>>>();
    k_gz0<<<Bb*Hh,128>>>(z0,Gw);
    k_wt<<<8192,256>>>(Wr,Wi);
    k_dD<<<Bb*Hh,256>>>(xi);
    k_fft_z0<<<Bb*8,256>>>(z0);
    k_fft_dx<<<Bb*Hh*64,256>>>();
    k_scan<<<Xx,256>>>();
    k_fft_out<<<Bb*Hh*64,256>>>(out);
}

// round 5
// speedup vs baseline: 1.1233x; 1.1233x over previous
#include <cuda_runtime.h>
#include <cuda_bf16.h>

typedef unsigned long long u64;

#define Bb 8
#define Hh 32
#define Ff 8
#define Xx 128
#define Tt 256
#define Ts 255

// ---------------- device scratch ----------------
__device__ float  g_Gz0[Bb*Hh*Xx*Ff];                 // [b][c][x][f]
__device__ float  g_dD[(size_t)Bb*Hh*Ts*Xx];          // [b][c][t][x]
__device__ float4 g_W4[(size_t)Xx*Hh*16*Hh];          // [k][c][jp][i] = (wr0,wr1,wi0,wi1)
__device__ float2 g_dx[(size_t)Ts*Hh*Bb*Xx];          // [t][c][b][k]
__device__ float2 g_zinit[Xx*Hh*Bb];                  // [k][h][b]
__device__ float2 g_zall[(size_t)Bb*Hh*Tt*Xx];        // [bh][t][k]
__device__ float2 g_twf[127], g_twi[127];

// ---------------- f32x2 helpers ----------------
__device__ __forceinline__ u64 f2fma(u64 a,u64 b,u64 c){u64 d;asm("fma.rn.f32x2 %0,%1,%2,%3;":"=l"(d):"l"(a),"l"(b),"l"(c));return d;}
__device__ __forceinline__ u64 f2add(u64 a,u64 b){u64 d;asm("add.rn.f32x2 %0,%1,%2;":"=l"(d):"l"(a),"l"(b));return d;}
__device__ __forceinline__ u64 pkd(float a){u64 d;asm("mov.b64 %0,{%1,%1};":"=l"(d):"f"(a));return d;}
__device__ __forceinline__ void upk(u64 v,float&a,float&b){asm("mov.b64 {%0,%1},%2;":"=f"(a),"=f"(b):"l"(v));}

// ---------------- twiddles ----------------
__global__ void k_twiddle(){
    int t=threadIdx.x;
    if(t<127){
        int l=1<<(31-__clz(t+1)); int j=t+1-l;
        float s,c; sincospif((float)j/(float)l,&s,&c);
        g_twf[t]=make_float2(c,-s); g_twi[t]=make_float2(c,s);
    }
}

// ---------------- Stockham radix-2, 64 threads per FFT ----------------
__device__ __forceinline__ float2* do_fft(float2* x,float2* y,const float2* tw,int bt){
    float2 *s=x,*d=y;
    #pragma unroll
    for(int st=0;st<7;st++){
        int l=1<<st, j=bt&(l-1), q=bt>>st;
        float2 aa=s[q*l+j], bb=s[q*l+j+64], w=tw[l-1+j];
        float br=w.x*bb.x-w.y*bb.y, bi=w.x*bb.y+w.y*bb.x;
        d[q*2*l+j]=make_float2(aa.x+br,aa.y+bi);
        d[q*2*l+j+l]=make_float2(aa.x-br,aa.y-bi);
        __syncthreads();
        float2* tmp=s; s=d; d=tmp;
    }
    return s;
}

// ---------------- Gz0[b][c][x][f] = sum_h Gw[c][f][h] z0[b][h][x] ------------
__global__ void k_gz0(const float* __restrict__ z0,const float* __restrict__ Gw){
    __shared__ float z0s[Hh][Xx];
    int blk=blockIdx.x, c=blk&31, b=blk>>5, x=threadIdx.x;
    for(int e=x;e<Hh*Xx;e+=128) z0s[e>>7][e&127]=z0[(size_t)b*Hh*Xx+e];
    __syncthreads();
    #pragma unroll
    for(int f=0;f<Ff;f++){
        float acc=0.f;
        #pragma unroll 8
        for(int h=0;h<Hh;h++) acc+=Gw[(c*Ff+f)*Hh+h]*z0s[h][x];
        g_Gz0[((size_t)blk*Xx+x)*Ff+f]=acc;
    }
}

// ---------------- W transpose via smem tiles: coalesced both ways ------------
// g_W4[k][c][jp][i] = (Wr[k,i,c,2jp],Wr[k,i,c,2jp+1],Wi[k,i,c,2jp],Wi[k,i,c,2jp+1])
__global__ void k_wt(const float* __restrict__ Wr,const float* __restrict__ Wi){
    __shared__ float sr[32][33], si[32][33];
    int blk=blockIdx.x, c=blk&31, kk=blk>>5, tid=threadIdx.x;
    for(int e=tid;e<1024;e+=256){
        int i=e>>5, j=e&31;
        size_t s=(((size_t)kk*Hh+i)*Hh+c)*Hh+j;
        sr[i][j]=Wr[s]; si[i][j]=Wi[s];
    }
    __syncthreads();
    for(int e=tid;e<512;e+=256){
        int i=e&31, jp=e>>5;
        g_W4[((size_t)blk*16+jp)*32+i]=
            make_float4(sr[i][2*jp],sr[i][2*jp+1],si[i][2*jp],si[i][2*jp+1]);
    }
}

// ---------------- dD[b][c][t][x] = sum_f Gz0*(xi[t+1]-xi[t]) ----------------
__global__ void k_dD(const float* __restrict__ xi){
    __shared__ float gs[32][8];
    __shared__ float tr[32][257];
    int blk=blockIdx.x;                // (b*32+c)*4 + xq
    int xq=blk&3, bc=blk>>2, b=bc>>5, tid=threadIdx.x;
    for(int e=tid;e<256;e+=256) gs[e>>3][e&7]=g_Gz0[((size_t)bc*Xx+xq*32)*Ff+e];
    __syncthreads();
    int t=tid;
    #pragma unroll 1
    for(int xs=0;xs<32;xs++){
        float acc=0.f;
        if(t<Ts){
            int x=xq*32+xs;
            #pragma unroll
            for(int f=0;f<Ff;f++){
                const float* p=xi+(((size_t)(b*Ff+f)*Xx)+x)*Tt+t;
                acc+=gs[xs][f]*(p[1]-p[0]);
            }
        }
        tr[xs][t]=acc;
    }
    __syncthreads();
    for(int e=tid;e<Ts*32;e+=256){
        int xs=e&31, tt=e>>5;
        g_dD[((size_t)bc*Ts+tt)*Xx+xq*32+xs]=tr[xs][tt];
    }
}

// ---------------- FFT of dD rows -> g_dx[t][c][b][k] (coalesced writes) ------
__global__ void k_fft_dx(){
    __shared__ float2 xb[4][128], yb[4][128], tws[127];
    int tid=threadIdx.x;
    for(int q=tid;q<127;q+=256) tws[q]=g_twf[q];
    int blk=blockIdx.x, tc=blk&63, bc=blk>>6, c=bc&31, b=bc>>5;
    for(int e=tid;e<512;e+=256){
        int sub=e>>7, xx=e&127, t=tc*4+sub;
        float v=(t<Ts)? g_dD[((size_t)bc*Ts+t)*Xx+xx] : 0.f;
        if(xx&1) v=-v;                              // fftshift
        xb[sub][xx]=make_float2(v,0.f);
    }
    __syncthreads();
    int sub=tid>>6, bt=tid&63;
    float2* r=do_fft(xb[sub],yb[sub],tws,bt);
    int t=tc*4+sub;
    if(t<Ts){
        size_t base=((size_t)t*256 + c*8 + b)*Xx;
        g_dx[base+bt]=r[bt];
        g_dx[base+bt+64]=r[bt+64];
    }
}

// ---------------- FFT of z0 -> g_zinit[k][h][b] ----------------
__global__ void k_fft_z0(const float* __restrict__ z0){
    __shared__ float2 xb[4][128], yb[4][128], tws[127];
    int tid=threadIdx.x;
    for(int q=tid;q<127;q+=256) tws[q]=g_twf[q];
    int blk=blockIdx.x, hc=blk&7, b=blk>>3;
    for(int e=tid;e<512;e+=256){
        int sub=e>>7, xx=e&127, h=hc*4+sub;
        float v=z0[((size_t)b*Hh+h)*Xx+xx];
        if(xx&1) v=-v;
        xb[sub][xx]=make_float2(v,0.f);
    }
    __syncthreads();
    int sub=tid>>6, bt=tid&63, h=hc*4+sub;
    float2* r=do_fft(xb[sub],yb[sub],tws,bt);
    g_zinit[((size_t)bt*Hh+h)*Bb+b]=r[bt];
    g_zinit[((size_t)(bt+64)*Hh+h)*Bb+b]=r[bt+64];
}

// ---------------- sequential CDE scan: one CTA per Fourier mode --------------
// packing axis = j-pairs: W float4 gives (wr0,wr1)/(wi0,wi1) u64 aliases, z is
// [b][j] so float4 loads give j-pair u64 aliases: zero packing MOVs.
__global__ void __launch_bounds__(256,1) k_scan(){
    __shared__ __align__(16) float zre_s[Bb][Hh], zim_s[Bb][Hh];
    __shared__ u64 dre_u[Hh][Bb], dim_u[Hh][Bb], dni_u[Hh][Bb];
    __shared__ float part_s[8][Hh][Bb][2];
    int tid=threadIdx.x, k=blockIdx.x;
    int cg=tid>>5, i=tid&31;
    int i2=tid>>3, b2=tid&7;
    {
        float2 v=g_zinit[(size_t)k*256+tid];        // tid = h*8+b
        zre_s[b2][i2]=v.x; zim_s[b2][i2]=v.y;
        g_zall[((size_t)(b2*Hh+i2)*Tt)*Xx+k]=v;
    }
    u64 m1=pkd(-1.f);
    float2 vdx=g_dx[(size_t)tid*Xx+k];              // prefetch t=0
    #pragma unroll 1
    for(int t=0;t<Ts;t++){
        dre_u[i2][b2]=pkd(vdx.x);
        dim_u[i2][b2]=pkd(vdx.y);
        dni_u[i2][b2]=pkd(-vdx.y);
        __syncthreads();
        if(t+1<Ts) vdx=g_dx[((size_t)(t+1)*256+tid)*Xx+k];
        u64 aRe[8],aIm[8];
        #pragma unroll
        for(int b=0;b<8;b++){aRe[b]=0ULL;aIm[b]=0ULL;}
        #pragma unroll 1
        for(int cc=0;cc<4;cc++){
            int c=cg*4+cc;
            const float4* Wc=g_W4+(((size_t)k*Hh+c)*16)*32+i;
            u64 rr[8],ii[8],ri[8],ir[8];
            #pragma unroll
            for(int b=0;b<8;b++){rr[b]=0ULL;ii[b]=0ULL;ri[b]=0ULL;ir[b]=0ULL;}
            #pragma unroll
            for(int jq=0;jq<8;jq++){
                float4 wA=__ldg(Wc+(2*jq)*32);
                float4 wB=__ldg(Wc+(2*jq+1)*32);
                u64 wr0=*(const u64*)&wA.x, wi0=*(const u64*)&wA.z;
                u64 wr1=*(const u64*)&wB.x, wi1=*(const u64*)&wB.z;
                #pragma unroll
                for(int b=0;b<8;b++){
                    float4 zr4=*(const float4*)&zre_s[b][4*jq];
                    float4 zi4=*(const float4*)&zim_s[b][4*jq];
                    u64 zr0=*(const u64*)&zr4.x, zr1=*(const u64*)&zr4.z;
                    u64 zi0=*(const u64*)&zi4.x, zi1=*(const u64*)&zi4.z;
                    rr[b]=f2fma(wr0,zr0,rr[b]); rr[b]=f2fma(wr1,zr1,rr[b]);
                    ii[b]=f2fma(wi0,zi0,ii[b]); ii[b]=f2fma(wi1,zi1,ii[b]);
                    ri[b]=f2fma(wr0,zi0,ri[b]); ri[b]=f2fma(wr1,zi1,ri[b]);
                    ir[b]=f2fma(wi0,zr0,ir[b]); ir[b]=f2fma(wi1,zr1,ir[b]);
                }
            }
            #pragma unroll
            for(int b=0;b<8;b++){
                u64 sre=f2fma(ii[b],m1,rr[b]);
                u64 sim=f2add(ri[b],ir[b]);
                u64 dre=dre_u[c][b], dim=dim_u[c][b], dni=dni_u[c][b];
                aRe[b]=f2fma(dre,sre,aRe[b]); aRe[b]=f2fma(dni,sim,aRe[b]);
                aIm[b]=f2fma(dre,sim,aIm[b]); aIm[b]=f2fma(dim,sre,aIm[b]);
            }
        }
        #pragma unroll
        for(int b=0;b<8;b++){
            float r0,r1,s0,s1;
            upk(aRe[b],r0,r1); upk(aIm[b],s0,s1);
            part_s[cg][i][b][0]=r0+r1;
            part_s[cg][i][b][1]=s0+s1;
        }
        __syncthreads();
        float sr=0.f,si=0.f;
        #pragma unroll
        for(int g=0;g<8;g++){
            float2 p=*(const float2*)&part_s[g][i2][b2][0];
            sr+=p.x; si+=p.y;
        }
        float nr=zre_s[b2][i2]+sr, ni=zim_s[b2][i2]+si;
        zre_s[b2][i2]=nr; zim_s[b2][i2]=ni;
        g_zall[((size_t)(b2*Hh+i2)*Tt+(t+1))*Xx+k]=make_float2(nr,ni);
    }
}

// ---------------- inverse FFT, 32 t per block, smem transpose ---------------
__global__ void k_fft_out(float* __restrict__ out){
    __shared__ float2 xb[4][128], yb[4][128], tws[127];
    __shared__ float tr[128][33];
    int tid=threadIdx.x;
    for(int q=tid;q<127;q+=256) tws[q]=g_twi[q];
    int blk=blockIdx.x, tg=blk&7, bh=blk>>3;
    int sub=tid>>6, bt=tid&63;
    #pragma unroll 1
    for(int rr8=0;rr8<8;rr8++){
        int t0=tg*32+rr8*4;
        __syncthreads();
        for(int e=tid;e<512;e+=256){
            int su=e>>7, kk=e&127;
            xb[su][kk]=g_zall[((size_t)bh*Tt+t0+su)*Xx+kk];
        }
        __syncthreads();
        float2* r=do_fft(xb[sub],yb[sub],tws,bt);
        int tt=rr8*4+sub;
        tr[bt][tt]=r[bt].x;
        tr[bt+64][tt]=r[bt+64].x;
    }
    __syncthreads();
    const float sc=1.f/128.f;
    for(int e=tid;e<4096;e+=256){
        int ttt=e&31, x=e>>5;
        float s=(x&1)? -sc:sc;                      // ifftshift sign
        out[((size_t)bh*Xx+x)*Tt+tg*32+ttt]=tr[x][ttt]*s;
    }
}

// ---------------- launch ----------------
extern "C" void kernel_launch(void* const* d_in,const int* in_sizes,int n_in,
                              void* d_out,int out_size){
    const float* z0=(const float*)d_in[0];
    const float* xi=(const float*)d_in[1];
    // d_in[2] = A : algebraically dead (cancels in dX)
    const float* Gw=(const float*)d_in[3];
    const float* Wr=(const float*)d_in[4];
    const float* Wi=(const float*)d_in[5];
    float* out=(float*)d_out;

    k_twiddle<<<1,128>>>();
    k_gz0<<<Bb*Hh,128>>>(z0,Gw);
    k_wt<<<Xx*Hh,256>>>(Wr,Wi);
    k_dD<<<Bb*Hh*4,256>>>(xi);
    k_fft_z0<<<Bb*8,256>>>(z0);
    k_fft_dx<<<Bb*Hh*64,256>>>();
    k_scan<<<Xx,256>>>();
    k_fft_out<<<Bb*Hh*8,256>>>(out);
}